// round 6
// baseline (speedup 1.0000x reference)
#include <cuda_runtime.h>
#include <cuda_bf16.h>
#include <math.h>

// Problem constants
#define B      256
#define NNEG   1000
#define H      3
#define D      128
#define CMAX   250          // neg indices < min(NUM_CLUSTER) = 250
#define EPSF   1e-6f
#define BPB    4            // b's per block
#define NBLK   (B / BPB)    // 64 blocks
#define NROWS  (H * CMAX)   // 750 centroid rows streamed per block

// Device globals (no allocation allowed)
__device__ float g_loss[B];               // per-sample loss
__device__ unsigned int g_done = 0;       // completion counter

__global__ void __launch_bounds__(1024, 1)
hirl_all(const float* __restrict__ se,
         const float* __restrict__ c0,
         const float* __restrict__ c1,
         const float* __restrict__ c2,
         const int* __restrict__ i2c0,
         const int* __restrict__ i2c1,
         const int* __restrict__ i2c2,
         const int* __restrict__ index,
         const int* __restrict__ neg,
         float* __restrict__ out) {
    __shared__ float4 se_s[12 * 32];      // 12 se rows [row][lane] (6 KB)
    __shared__ float  sInvSe[12];         // 1/||se|| per row
    __shared__ float  S_s[BPB * H * 256]; // local sim matrix (12 KB)
    __shared__ float  posmul_s[BPB];
    __shared__ int    lab_s[BPB][H];
    __shared__ float  rQ[BPB][8];
    __shared__ float  cQ[BPB][8];
    __shared__ int    sLast;

    const int tid  = threadIdx.x;
    const int w    = tid >> 5;
    const int lane = tid & 31;
    const int b0   = blockIdx.x * BPB;

    // ---- Phase -1: pull this block's neg triples into registers (hides DRAM) ----
    const int q = tid >> 8, local = tid & 255;    // quarter q handles b0+q
    const bool active = (local < 250);            // 250 thr x 4 negs = 1000
    int4 na, nb, nc;
    if (active) {
        const int4* p = (const int4*)(neg + ((size_t)(b0 + q) * NNEG + local * 4) * H);
        na = p[0]; nb = p[1]; nc = p[2];          // 4 consecutive (i0,i1,i2) triples
    }

    // ---- Phase 0: se rows + norms (warps 0-11), pos path (warps 12-15) ----
    if (w < 12) {
        // row w = (b_local, h): b_local = w/3, h = w%3
        int bl = w / 3, h = w - bl * 3;
        float4 v = ((const float4*)(se + ((size_t)(b0 + bl) * H + h) * D))[lane];
        se_s[w * 32 + lane] = v;
        float s = v.x * v.x + v.y * v.y + v.z * v.z + v.w * v.w;
        #pragma unroll
        for (int o = 16; o > 0; o >>= 1) s += __shfl_xor_sync(0xffffffffu, s, o);
        if (lane == 0) sInvSe[w] = 1.0f / fmaxf(sqrtf(s), 1e-12f);
    } else if (w < 16) {
        // pos path for b = b0 + (w-12); labels may index full tables
        int b = b0 + (w - 12);
        int idx = index[b];
        int lab0 = i2c0[idx], lab1 = i2c1[idx], lab2 = i2c2[idx];
        float4 cv0 = ((const float4*)(c0 + (size_t)lab0 * D))[lane];
        float4 cv1 = ((const float4*)(c1 + (size_t)lab1 * D))[lane];
        float4 cv2 = ((const float4*)(c2 + (size_t)lab2 * D))[lane];
        float4 sv0 = ((const float4*)(se + ((size_t)b * H + 0) * D))[lane];
        float4 sv1 = ((const float4*)(se + ((size_t)b * H + 1) * D))[lane];
        float4 sv2 = ((const float4*)(se + ((size_t)b * H + 2) * D))[lane];
        float prod = 1.0f;
        #pragma unroll
        for (int h = 0; h < H; h++) {
            float4 cv = (h == 0) ? cv0 : (h == 1) ? cv1 : cv2;
            float4 sv = (h == 0) ? sv0 : (h == 1) ? sv1 : sv2;
            float cc = cv.x * cv.x + cv.y * cv.y + cv.z * cv.z + cv.w * cv.w;
            float ee = sv.x * sv.x + sv.y * sv.y + sv.z * sv.z + sv.w * sv.w;
            float dd = cv.x * sv.x + cv.y * sv.y + cv.z * sv.z + cv.w * sv.w;
            #pragma unroll
            for (int o = 16; o > 0; o >>= 1) {
                cc += __shfl_xor_sync(0xffffffffu, cc, o);
                ee += __shfl_xor_sync(0xffffffffu, ee, o);
                dd += __shfl_xor_sync(0xffffffffu, dd, o);
            }
            float s = dd / (fmaxf(sqrtf(cc), 1e-12f) * fmaxf(sqrtf(ee), 1e-12f));
            prod *= (s + 1.0f) * 0.5f;
        }
        if (lane == 0) {
            posmul_s[w - 12] = prod;
            lab_s[w - 12][0] = lab0;
            lab_s[w - 12][1] = lab1;
            lab_s[w - 12][2] = lab2;
        }
    }
    __syncthreads();

    // ---- Phase 1: stream 750 centroid rows, 1 norm + 4 dots per row ----
    for (int r = w; r < NROWS; r += 32) {
        int h = r / CMAX;              // 0..2
        int c = r - h * CMAX;          // 0..249
        const float* cents = (h == 0) ? c0 : (h == 1) ? c1 : c2;
        float4 cv = ((const float4*)(cents + (size_t)c * D))[lane];

        float4 s0 = se_s[(0 * H + h) * 32 + lane];
        float4 s1 = se_s[(1 * H + h) * 32 + lane];
        float4 s2 = se_s[(2 * H + h) * 32 + lane];
        float4 s3 = se_s[(3 * H + h) * 32 + lane];

        float ss = cv.x * cv.x + cv.y * cv.y + cv.z * cv.z + cv.w * cv.w;
        float d0 = cv.x * s0.x + cv.y * s0.y + cv.z * s0.z + cv.w * s0.w;
        float d1 = cv.x * s1.x + cv.y * s1.y + cv.z * s1.z + cv.w * s1.w;
        float d2 = cv.x * s2.x + cv.y * s2.y + cv.z * s2.z + cv.w * s2.w;
        float d3 = cv.x * s3.x + cv.y * s3.y + cv.z * s3.z + cv.w * s3.w;
        #pragma unroll
        for (int o = 16; o > 0; o >>= 1) {
            ss += __shfl_xor_sync(0xffffffffu, ss, o);
            d0 += __shfl_xor_sync(0xffffffffu, d0, o);
            d1 += __shfl_xor_sync(0xffffffffu, d1, o);
            d2 += __shfl_xor_sync(0xffffffffu, d2, o);
            d3 += __shfl_xor_sync(0xffffffffu, d3, o);
        }
        if (lane == 0) {
            float invc = 1.0f / fmaxf(sqrtf(ss), 1e-12f);
            int off = h * 256 + c;
            S_s[0 * 768 + off] = (d0 * invc * sInvSe[0 * H + h] + 1.0f) * 0.5f;
            S_s[1 * 768 + off] = (d1 * invc * sInvSe[1 * H + h] + 1.0f) * 0.5f;
            S_s[2 * 768 + off] = (d2 * invc * sInvSe[2 * H + h] + 1.0f) * 0.5f;
            S_s[3 * 768 + off] = (d3 * invc * sInvSe[3 * H + h] + 1.0f) * 0.5f;
        }
    }
    __syncthreads();

    // ---- Phase 2: loss from register-held neg indices + smem S ----
    float sumL = 0.0f, cnt = 0.0f;
    if (active) {
        const int lab0 = lab_s[q][0], lab1 = lab_s[q][1], lab2 = lab_s[q][2];
        const float* Sq = S_s + q * 768;
        int idx0[4] = { na.x, na.w, nb.z, nc.y };
        int idx1[4] = { na.y, nb.x, nb.w, nc.z };
        int idx2[4] = { na.z, nb.y, nc.x, nc.w };
        #pragma unroll
        for (int k = 0; k < 4; k++) {
            int i0 = idx0[k], i1 = idx1[k], i2 = idx2[k];
            float prod = Sq[i0] * Sq[256 + i1] * Sq[512 + i2];
            bool tn = (i0 != lab0) || (i1 != lab1) || (i2 != lab2);
            if (tn) {
                sumL += -__logf(1.0f - prod + EPSF);
                cnt  += 1.0f;
            }
        }
    }
    #pragma unroll
    for (int o = 16; o > 0; o >>= 1) {
        sumL += __shfl_xor_sync(0xffffffffu, sumL, o);
        cnt  += __shfl_xor_sync(0xffffffffu, cnt,  o);
    }
    if (lane == 0) { rQ[q][w & 7] = sumL; cQ[q][w & 7] = cnt; }
    __syncthreads();

    if ((tid & 255) == 0) {          // 4 threads, one per quarter
        float sL = 0.0f, sC = 0.0f;
        #pragma unroll
        for (int i = 0; i < 8; i++) { sL += rQ[q][i]; sC += cQ[q][i]; }
        float negl = sL / (sC + EPSF);
        float posl = -__logf(posmul_s[q] + EPSF);
        g_loss[b0 + q] = 0.5f * (posl + negl);
        __threadfence();             // flush this writer's g_loss
    }
    __syncthreads();

    if (tid == 0) {
        unsigned int t = atomicAdd(&g_done, 1u);
        sLast = (t == (unsigned)(NBLK - 1)) ? 1 : 0;
    }
    __syncthreads();

    // ---- Last block: deterministic final mean over B=256 losses ----
    if (sLast) {
        __threadfence();
        float v = 0.0f;
        if (tid < B) v = *((volatile float*)&g_loss[tid]);
        if (tid < 256) {
            #pragma unroll
            for (int o = 16; o > 0; o >>= 1) v += __shfl_xor_sync(0xffffffffu, v, o);
            if (lane == 0) rQ[0][w] = v;   // w in 0..7
        }
        __syncthreads();
        if (tid == 0) {
            float total = 0.0f;
            #pragma unroll
            for (int i = 0; i < 8; i++) total += rQ[0][i];
            out[0] = total * (1.0f / (float)B);
            g_done = 0;   // reset for next graph replay
        }
    }
}

// ---------------------------------------------------------------------------
extern "C" void kernel_launch(void* const* d_in, const int* in_sizes, int n_in,
                              void* d_out, int out_size) {
    const float* se  = (const float*)d_in[0];
    const float* c0  = (const float*)d_in[1];
    const float* c1  = (const float*)d_in[2];
    const float* c2  = (const float*)d_in[3];
    const int* i2c0  = (const int*)d_in[4];
    const int* i2c1  = (const int*)d_in[5];
    const int* i2c2  = (const int*)d_in[6];
    const int* index = (const int*)d_in[7];
    const int* neg   = (const int*)d_in[8];
    float* out = (float*)d_out;

    hirl_all<<<NBLK, 1024>>>(se, c0, c1, c2, i2c0, i2c1, i2c2, index, neg, out);
}